// round 2
// baseline (speedup 1.0000x reference)
#include <cuda_runtime.h>
#include <cuda_bf16.h>

typedef unsigned long long u64;

#define NBH 1024   // B*H
#define TT  4
#define DK  128
#define DV  256

// ---- packed f32x2 helpers (Blackwell sm_103a) ----
__device__ __forceinline__ u64 pk2(float x, float y){
    u64 r; asm("mov.b64 %0, {%1,%2};" : "=l"(r) : "f"(x), "f"(y)); return r;
}
__device__ __forceinline__ u64 fma2(u64 a, u64 b, u64 c){
    u64 d; asm("fma.rn.f32x2 %0, %1, %2, %3;" : "=l"(d) : "l"(a), "l"(b), "l"(c)); return d;
}
__device__ __forceinline__ u64 add2(u64 a, u64 b){
    u64 d; asm("add.rn.f32x2 %0, %1, %2;" : "=l"(d) : "l"(a), "l"(b)); return d;
}
__device__ __forceinline__ u64 mul2(u64 a, u64 b){
    u64 d; asm("mul.rn.f32x2 %0, %1, %2;" : "=l"(d) : "l"(a), "l"(b)); return d;
}

// One CTA = one (b,h) x one quarter of Dv (64 cols).
//   cg = tid & 15  -> 4 consecutive cols      (16 col-groups * 4 = 64 cols)
//   rg = tid >> 4  -> 8 consecutive rows      (16 row-groups * 8 = 128 rows)
// State slice 8x4 fp32 lives in registers as 8 x (u64,u64).
// Decay factored out (state = c * S'). q-readout fused into the k-readout
// sweep via  S_new.q = S_old.q + (k.q) * d  -> single reduction barrier/step.
// Reduction buffers double-buffered by step parity -> no 2nd barrier.
__global__ __launch_bounds__(256, 3)
void gdn_step_kernel(const float* __restrict__ q, const float* __restrict__ k,
                     const float* __restrict__ v, const float* __restrict__ g,
                     const float* __restrict__ beta, const float* __restrict__ s0,
                     float* __restrict__ out, float* __restrict__ sout)
{
    const int bh    = blockIdx.x >> 2;
    const int quad  = blockIdx.x & 3;
    const int vbase = quad * 64;
    const int tid   = threadIdx.x;
    const int cg    = tid & 15;    // column group (4 cols)
    const int rg    = tid >> 4;    // row group (8 rows)
    const int k0    = rg * 8;
    const int v0    = vbase + cg * 4;

    __shared__ __align__(16) float qs[TT * DK];
    __shared__ __align__(16) float ks[TT * DK];
    __shared__ __align__(16) float vs[TT * 64];
    __shared__ float gs[TT], bs[TT];
    __shared__ ulonglong2 redK[2][256];   // k-dot partials (x,y packed pairs)
    __shared__ ulonglong2 redQ[2][256];   // q-dot partials
    __shared__ float      redS[2][256];   // k.q scalar partials

    // ---- front-batched state load: 8 x LDG.128 streaming, coalesced ----
    const size_t sbase = (size_t)bh * (DK * DV);
    ulonglong2 S[8];
#pragma unroll
    for (int kk = 0; kk < 8; kk++){
        float4 f = __ldcs((const float4*)(s0 + sbase + (size_t)(k0 + kk) * DV + v0));
        S[kk].x = pk2(f.x, f.y);
        S[kk].y = pk2(f.z, f.w);
    }

    // ---- stage q/k/v/g/beta into smem ----
    {
        const int qb = bh * (TT * DK);
        for (int i = tid; i < TT * DK; i += 256){ qs[i] = q[qb + i]; ks[i] = k[qb + i]; }
        const int vb = bh * (TT * DV);
        {
            int t = tid >> 6, j = tid & 63;           // 256 threads = 4*64 exactly
            vs[tid] = v[vb + t * DV + vbase + j];
        }
        if (tid < TT){ gs[tid] = g[bh * TT + tid]; bs[tid] = beta[bh * TT + tid]; }
    }
    __syncthreads();

    float c = 1.0f;   // cumulative decay; true state = c * S'
#pragma unroll
    for (int t = 0; t < TT; t++){
        const int buf = t & 1;
        c *= __expf(gs[t]);

        // one sweep over OLD state: k-dot, q-dot, and scalar k.q partials
        u64 ax = 0ull, ay = 0ull, ox = 0ull, oy = 0ull;
        float kqp = 0.0f;
#pragma unroll
        for (int kk = 0; kk < 8; kk++){
            float ktf = ks[t * DK + k0 + kk];
            float qtf = qs[t * DK + k0 + kk];
            u64 kt2 = pk2(ktf, ktf);
            u64 qt2 = pk2(qtf, qtf);
            ax = fma2(S[kk].x, kt2, ax);
            ay = fma2(S[kk].y, kt2, ay);
            ox = fma2(S[kk].x, qt2, ox);
            oy = fma2(S[kk].y, qt2, oy);
            kqp = fmaf(ktf, qtf, kqp);
        }
        redK[buf][tid] = make_ulonglong2(ax, ay);
        redQ[buf][tid] = make_ulonglong2(ox, oy);
        redS[buf][tid] = kqp;
        __syncthreads();

        // reduce 16 row-group partials
        u64 sx = 0ull, sy = 0ull, qx = 0ull, qy = 0ull;
        float kq = 0.0f;
#pragma unroll
        for (int r = 0; r < 16; r++){
            int idx = r * 16 + cg;
            ulonglong2 pk_ = redK[buf][idx];
            ulonglong2 pq_ = redQ[buf][idx];
            sx = add2(sx, pk_.x); sy = add2(sy, pk_.y);
            qx = add2(qx, pq_.x); qy = add2(qy, pq_.y);
            kq += redS[buf][r * 16 + cg];
        }

        // d' = (v - c*kv) * beta / c   (update vector for S')
        ulonglong2 vv;
        {
            const float* vp = &vs[t * 64 + cg * 4];
            vv.x = pk2(vp[0], vp[1]);
            vv.y = pk2(vp[2], vp[3]);
        }
        float bic = bs[t] / c;
        u64 nc2  = pk2(-c, -c);
        u64 bic2 = pk2(bic, bic);
        u64 dx = mul2(fma2(sx, nc2, vv.x), bic2);
        u64 dy = mul2(fma2(sy, nc2, vv.y), bic2);

        // out_t = c * (S'_old.q + (k.q) * d')   -- row-group 0 writes
        if (rg == 0){
            u64 kq2 = pk2(kq, kq);
            u64 c2  = pk2(c, c);
            ulonglong2 o;
            o.x = mul2(fma2(kq2, dx, qx), c2);
            o.y = mul2(fma2(kq2, dy, qy), c2);
            *(ulonglong2*)(out + (size_t)(bh * TT + t) * DV + v0) = o;
        }

        // rank-1 update of S'
#pragma unroll
        for (int kk = 0; kk < 8; kk++){
            float ktf = ks[t * DK + k0 + kk];
            u64 kt2 = pk2(ktf, ktf);
            S[kk].x = fma2(kt2, dx, S[kk].x);
            S[kk].y = fma2(kt2, dy, S[kk].y);
        }
        // no 2nd barrier: red buffers are parity double-buffered
    }

    // ---- final state writeback: state = c * S', streaming stores ----
    u64 c2 = pk2(c, c);
#pragma unroll
    for (int kk = 0; kk < 8; kk++){
        u64 wx = mul2(S[kk].x, c2);
        u64 wy = mul2(S[kk].y, c2);
        float4 f;
        asm("mov.b64 {%0,%1}, %2;" : "=f"(f.x), "=f"(f.y) : "l"(wx));
        asm("mov.b64 {%0,%1}, %2;" : "=f"(f.z), "=f"(f.w) : "l"(wy));
        __stcs((float4*)(sout + sbase + (size_t)(k0 + kk) * DV + v0), f);
    }
}

extern "C" void kernel_launch(void* const* d_in, const int* in_sizes, int n_in,
                              void* d_out, int out_size)
{
    const float* q    = (const float*)d_in[0];
    const float* k    = (const float*)d_in[1];
    const float* v    = (const float*)d_in[2];
    const float* g    = (const float*)d_in[3];
    const float* beta = (const float*)d_in[4];
    const float* s0   = (const float*)d_in[5];
    float* out  = (float*)d_out;
    float* sout = out + (size_t)NBH * TT * DV;   // state follows the T outputs

    gdn_step_kernel<<<NBH * 4, 256>>>(q, k, v, g, beta, s0, out, sout);
}

// round 3
// speedup vs baseline: 1.6208x; 1.6208x over previous
#include <cuda_runtime.h>
#include <cuda_bf16.h>

typedef unsigned long long u64;

#define NBH 1024   // B*H
#define TT  4
#define DK  128
#define DV  256

// ---- packed f32x2 helpers (Blackwell sm_103a) ----
__device__ __forceinline__ u64 pk2(float x, float y){
    u64 r; asm("mov.b64 %0, {%1,%2};" : "=l"(r) : "f"(x), "f"(y)); return r;
}
__device__ __forceinline__ void up2(u64 a, float& x, float& y){
    asm("mov.b64 {%0,%1}, %2;" : "=f"(x), "=f"(y) : "l"(a));
}
__device__ __forceinline__ u64 fma2(u64 a, u64 b, u64 c){
    u64 d; asm("fma.rn.f32x2 %0, %1, %2, %3;" : "=l"(d) : "l"(a), "l"(b), "l"(c)); return d;
}
__device__ __forceinline__ u64 mul2(u64 a, u64 b){
    u64 d; asm("mul.rn.f32x2 %0, %1, %2;" : "=l"(d) : "l"(a), "l"(b)); return d;
}

// One CTA = one (b,h) x one quarter of Dv (64 cols).
//   cg = tid & 15  -> 4 consecutive cols   (16 cgs * 4 = 64 cols)
//   rg = tid >> 4  -> 8 consecutive rows   (16 rgs * 8 = 128 rows)
// State slice 8x4 fp32 in registers (8 x ulonglong2 = 32 regs).
// Reduction = 3-stage transposed scheme:
//   stage1: each thread writes 9 partial floats (stride-9, conflict-free)
//   stage2: 144 threads: thread (f,cg) sums the 16 row-group partials of one
//           (cg, field) -> sums[cg][f]
//   stage3: everyone reads its cg's 9 sums, computes d locally.
// kq fusion: out = c*(S'_old.q + (k.q)*d')  -> one reduction per step.
__global__ __launch_bounds__(256, 4)
void gdn_step_kernel(const float* __restrict__ q, const float* __restrict__ k,
                     const float* __restrict__ v, const float* __restrict__ g,
                     const float* __restrict__ beta, const float* __restrict__ s0,
                     float* __restrict__ out, float* __restrict__ sout)
{
    const int bh    = blockIdx.x >> 2;
    const int quad  = blockIdx.x & 3;
    const int vbase = quad * 64;
    const int tid   = threadIdx.x;
    const int cg    = tid & 15;    // column group (4 cols)
    const int rg    = tid >> 4;    // row group (8 rows)
    const int k0    = rg * 8;
    const int v0    = vbase + cg * 4;

    __shared__ float qs[TT * DK];
    __shared__ float ks[TT * DK];
    __shared__ __align__(16) float vs[TT * 64];
    __shared__ float gs[TT], bs[TT];
    __shared__ float red[2][256 * 9];    // per-thread partials, stride 9
    __shared__ float sums[2][16 * 9];    // per-cg reduced sums

    // ---- front-batched state load: 8 x LDG.128 streaming, coalesced ----
    const size_t sbase = (size_t)bh * (DK * DV);
    ulonglong2 S[8];
#pragma unroll
    for (int kk = 0; kk < 8; kk++){
        float4 f = __ldcs((const float4*)(s0 + sbase + (size_t)(k0 + kk) * DV + v0));
        S[kk].x = pk2(f.x, f.y);
        S[kk].y = pk2(f.z, f.w);
    }

    // ---- stage q/k/v/g/beta into smem ----
    {
        const int qb = bh * (TT * DK);
        for (int i = tid; i < TT * DK; i += 256){ qs[i] = q[qb + i]; ks[i] = k[qb + i]; }
        const int vb = bh * (TT * DV);
        {
            int t = tid >> 6, j = tid & 63;      // 256 = 4*64 exactly
            vs[tid] = v[vb + t * DV + vbase + j];
        }
        if (tid < TT){ gs[tid] = g[bh * TT + tid]; bs[tid] = beta[bh * TT + tid]; }
    }
    __syncthreads();

    float c = 1.0f;   // cumulative decay; true state = c * S'
#pragma unroll
    for (int t = 0; t < TT; t++){
        const int buf = t & 1;
        c *= __expf(gs[t]);

        // one sweep over OLD state: k-dot, q-dot, k.q partials
        u64 ax = 0ull, ay = 0ull, ox = 0ull, oy = 0ull;
        float kqp = 0.0f;
#pragma unroll
        for (int kk = 0; kk < 8; kk++){
            float ktf = ks[t * DK + k0 + kk];
            float qtf = qs[t * DK + k0 + kk];
            u64 kt2 = pk2(ktf, ktf);
            u64 qt2 = pk2(qtf, qtf);
            ax = fma2(S[kk].x, kt2, ax);
            ay = fma2(S[kk].y, kt2, ay);
            ox = fma2(S[kk].x, qt2, ox);
            oy = fma2(S[kk].y, qt2, oy);
            kqp = fmaf(ktf, qtf, kqp);
        }
        // stage1: write 9 partials (word stride 9 -> conflict-free)
        {
            float* r = &red[buf][tid * 9];
            up2(ax, r[0], r[1]);
            up2(ay, r[2], r[3]);
            up2(ox, r[4], r[5]);
            up2(oy, r[6], r[7]);
            r[8] = kqp;
        }
        __syncthreads();

        // stage2: transposed reduce -- thread (f, cg2) sums 16 row groups
        if (tid < 144){
            int f   = tid >> 4;
            int cg2 = tid & 15;
            float s = 0.0f;
#pragma unroll
            for (int r2 = 0; r2 < 16; r2++)
                s += red[buf][(r2 * 16 + cg2) * 9 + f];
            sums[buf][cg2 * 9 + f] = s;
        }
        __syncthreads();

        // stage3: everyone reads its cg's sums, computes d' locally
        const float* sp = &sums[buf][cg * 9];
        u64 sx = pk2(sp[0], sp[1]);
        u64 sy = pk2(sp[2], sp[3]);
        u64 qx = pk2(sp[4], sp[5]);
        u64 qy = pk2(sp[6], sp[7]);
        float kq = sp[8];

        float4 vvf = *(const float4*)&vs[t * 64 + cg * 4];
        u64 vvx = pk2(vvf.x, vvf.y);
        u64 vvy = pk2(vvf.z, vvf.w);

        float bic = bs[t] / c;                  // beta / c
        u64 nc2  = pk2(-c, -c);
        u64 bic2 = pk2(bic, bic);
        u64 dx = mul2(fma2(sx, nc2, vvx), bic2);
        u64 dy = mul2(fma2(sy, nc2, vvy), bic2);

        // out_t = c * (S'_old.q + (k.q) * d')  -- one row group writes
        if (rg == 0){
            u64 kq2 = pk2(kq, kq);
            u64 c2  = pk2(c, c);
            ulonglong2 o;
            o.x = mul2(fma2(kq2, dx, qx), c2);
            o.y = mul2(fma2(kq2, dy, qy), c2);
            *(ulonglong2*)(out + (size_t)(bh * TT + t) * DV + v0) = o;
        }

        // rank-1 update of S'
#pragma unroll
        for (int kk = 0; kk < 8; kk++){
            float ktf = ks[t * DK + k0 + kk];
            u64 kt2 = pk2(ktf, ktf);
            S[kk].x = fma2(kt2, dx, S[kk].x);
            S[kk].y = fma2(kt2, dy, S[kk].y);
        }
    }

    // ---- final state writeback: state = c * S', streaming stores ----
    u64 c2 = pk2(c, c);
#pragma unroll
    for (int kk = 0; kk < 8; kk++){
        u64 wx = mul2(S[kk].x, c2);
        u64 wy = mul2(S[kk].y, c2);
        float4 f;
        up2(wx, f.x, f.y);
        up2(wy, f.z, f.w);
        __stcs((float4*)(sout + sbase + (size_t)(k0 + kk) * DV + v0), f);
    }
}

extern "C" void kernel_launch(void* const* d_in, const int* in_sizes, int n_in,
                              void* d_out, int out_size)
{
    const float* q    = (const float*)d_in[0];
    const float* k    = (const float*)d_in[1];
    const float* v    = (const float*)d_in[2];
    const float* g    = (const float*)d_in[3];
    const float* beta = (const float*)d_in[4];
    const float* s0   = (const float*)d_in[5];
    float* out  = (float*)d_out;
    float* sout = out + (size_t)NBH * TT * DV;   // state follows the T outputs

    gdn_step_kernel<<<NBH * 4, 256>>>(q, k, v, g, beta, s0, out, sout);
}

// round 4
// speedup vs baseline: 1.6225x; 1.0011x over previous
#include <cuda_runtime.h>
#include <cuda_bf16.h>

typedef unsigned long long u64;

#define NBH 1024   // B*H
#define TT  4
#define DK  128
#define DV  256

// ---- packed f32x2 helpers (Blackwell sm_103a) ----
__device__ __forceinline__ u64 pk2(float x, float y){
    u64 r; asm("mov.b64 %0, {%1,%2};" : "=l"(r) : "f"(x), "f"(y)); return r;
}
__device__ __forceinline__ void up2(u64 a, float& x, float& y){
    asm("mov.b64 {%0,%1}, %2;" : "=f"(x), "=f"(y) : "l"(a));
}
__device__ __forceinline__ u64 fma2(u64 a, u64 b, u64 c){
    u64 d; asm("fma.rn.f32x2 %0, %1, %2, %3;" : "=l"(d) : "l"(a), "l"(b), "l"(c)); return d;
}
__device__ __forceinline__ u64 mul2(u64 a, u64 b){
    u64 d; asm("mul.rn.f32x2 %0, %1, %2;" : "=l"(d) : "l"(a), "l"(b)); return d;
}

// One CTA = one (b,h) x one quarter of Dv (64 cols).
//   cg = tid & 15  -> 4 consecutive cols   (16 cgs * 4 = 64 cols)
//   rg = tid >> 4  -> 8 consecutive rows   (16 rgs * 8 = 128 rows)
// State slice 8x4 fp32 in registers. Decay factored out (state = c*S').
// kq fusion: out = c*(S'_old.q + (k.q)*d')  -> ONE reduction per step.
// 3-stage transposed reduction, all smem traffic vectorized:
//   stage1: STS.128 x2 + STS.32 into split arrays (conflict-free)
//   stage2: 144 threads transpose-sum 16 row-groups per (cg,field)
//   stage3: LDS.128 x2 broadcast + scalar
__global__ __launch_bounds__(256, 4)
void gdn_step_kernel(const float* __restrict__ q, const float* __restrict__ k,
                     const float* __restrict__ v, const float* __restrict__ g,
                     const float* __restrict__ beta, const float* __restrict__ s0,
                     float* __restrict__ out, float* __restrict__ sout)
{
    const int bh    = blockIdx.x >> 2;
    const int quad  = blockIdx.x & 3;
    const int vbase = quad * 64;
    const int tid   = threadIdx.x;
    const int cg    = tid & 15;    // column group (4 cols)
    const int rg    = tid >> 4;    // row group (8 rows)
    const int k0    = rg * 8;
    const int v0    = vbase + cg * 4;

    __shared__ __align__(16) float qs[TT * DK];
    __shared__ __align__(16) float ks[TT * DK];
    __shared__ __align__(16) float vs[TT * 64];
    __shared__ float gs[TT], bs[TT];
    __shared__ float4 redA[2][256];    // k-dot partials (4 cols)
    __shared__ float4 redB[2][256];    // q-dot partials (4 cols)
    __shared__ float  redC[2][256];    // k.q scalar partials
    __shared__ float4 sumsA[2][16];    // reduced k-dot per cg
    __shared__ float4 sumsB[2][16];    // reduced q-dot per cg
    __shared__ float  sumsC[2][16];    // reduced k.q per cg

    // ---- front-batched state load: 8 x LDG.128 streaming, coalesced ----
    const size_t sbase = (size_t)bh * (DK * DV);
    ulonglong2 S[8];
#pragma unroll
    for (int kk = 0; kk < 8; kk++){
        float4 f = __ldcs((const float4*)(s0 + sbase + (size_t)(k0 + kk) * DV + v0));
        S[kk].x = pk2(f.x, f.y);
        S[kk].y = pk2(f.z, f.w);
    }

    // ---- stage q/k/v/g/beta into smem ----
    {
        const int qb = bh * (TT * DK);
        for (int i = tid; i < TT * DK; i += 256){ qs[i] = q[qb + i]; ks[i] = k[qb + i]; }
        const int vb = bh * (TT * DV);
        {
            int t = tid >> 6, j = tid & 63;      // 256 = 4*64 exactly
            vs[tid] = v[vb + t * DV + vbase + j];
        }
        if (tid < TT){ gs[tid] = g[bh * TT + tid]; bs[tid] = beta[bh * TT + tid]; }
    }
    __syncthreads();

    float c = 1.0f;   // cumulative decay; true state = c * S'
#pragma unroll
    for (int t = 0; t < TT; t++){
        const int buf = t & 1;
        c *= __expf(gs[t]);

        // vectorized k/q fetch for this thread's 8 rows (2x LDS.128 each)
        float4 kA = *(const float4*)&ks[t * DK + k0];
        float4 kB = *(const float4*)&ks[t * DK + k0 + 4];
        float4 qA = *(const float4*)&qs[t * DK + k0];
        float4 qB = *(const float4*)&qs[t * DK + k0 + 4];
        float kf[8] = {kA.x, kA.y, kA.z, kA.w, kB.x, kB.y, kB.z, kB.w};
        float qf[8] = {qA.x, qA.y, qA.z, qA.w, qB.x, qB.y, qB.z, qB.w};

        // one sweep over OLD state: k-dot, q-dot, k.q partials
        u64 ax = 0ull, ay = 0ull, ox = 0ull, oy = 0ull;
        float kqp = 0.0f;
#pragma unroll
        for (int kk = 0; kk < 8; kk++){
            u64 kt2 = pk2(kf[kk], kf[kk]);
            u64 qt2 = pk2(qf[kk], qf[kk]);
            ax = fma2(S[kk].x, kt2, ax);
            ay = fma2(S[kk].y, kt2, ay);
            ox = fma2(S[kk].x, qt2, ox);
            oy = fma2(S[kk].y, qt2, oy);
            kqp = fmaf(kf[kk], qf[kk], kqp);
        }
        // stage1: vector writes, lane-stride 16B -> conflict-free STS.128
        {
            float4 a, b;
            up2(ax, a.x, a.y); up2(ay, a.z, a.w);
            up2(ox, b.x, b.y); up2(oy, b.z, b.w);
            redA[buf][tid] = a;
            redB[buf][tid] = b;
            redC[buf][tid] = kqp;
        }
        __syncthreads();

        // stage2: transposed reduce -- thread (f, cg2) sums 16 row groups
        if (tid < 144){
            int f   = tid >> 4;     // 0..8
            int cg2 = tid & 15;
            float s = 0.0f;
            if (f < 4){
#pragma unroll
                for (int r2 = 0; r2 < 16; r2++)
                    s += ((const float*)&redA[buf][r2 * 16 + cg2])[f];
                ((float*)&sumsA[buf][cg2])[f] = s;
            } else if (f < 8){
                int f2 = f - 4;
#pragma unroll
                for (int r2 = 0; r2 < 16; r2++)
                    s += ((const float*)&redB[buf][r2 * 16 + cg2])[f2];
                ((float*)&sumsB[buf][cg2])[f2] = s;
            } else {
#pragma unroll
                for (int r2 = 0; r2 < 16; r2++)
                    s += redC[buf][r2 * 16 + cg2];
                sumsC[buf][cg2] = s;
            }
        }
        __syncthreads();

        // stage3: vector broadcast reads, compute d' locally
        float4 sk = sumsA[buf][cg];
        float4 sq = sumsB[buf][cg];
        float  kq = sumsC[buf][cg];
        u64 sx = pk2(sk.x, sk.y), sy = pk2(sk.z, sk.w);
        u64 qx = pk2(sq.x, sq.y), qy = pk2(sq.z, sq.w);

        float4 vvf = *(const float4*)&vs[t * 64 + cg * 4];
        u64 vvx = pk2(vvf.x, vvf.y);
        u64 vvy = pk2(vvf.z, vvf.w);

        float bic = bs[t] / c;                  // beta / c
        u64 nc2  = pk2(-c, -c);
        u64 bic2 = pk2(bic, bic);
        u64 dx = mul2(fma2(sx, nc2, vvx), bic2);
        u64 dy = mul2(fma2(sy, nc2, vvy), bic2);

        // out_t = c * (S'_old.q + (k.q) * d')  -- one row group writes
        if (rg == 0){
            u64 kq2 = pk2(kq, kq);
            u64 c2  = pk2(c, c);
            ulonglong2 o;
            o.x = mul2(fma2(kq2, dx, qx), c2);
            o.y = mul2(fma2(kq2, dy, qy), c2);
            *(ulonglong2*)(out + (size_t)(bh * TT + t) * DV + v0) = o;
        }

        // rank-1 update of S'
#pragma unroll
        for (int kk = 0; kk < 8; kk++){
            u64 kt2 = pk2(kf[kk], kf[kk]);
            S[kk].x = fma2(kt2, dx, S[kk].x);
            S[kk].y = fma2(kt2, dy, S[kk].y);
        }
    }

    // ---- final state writeback: state = c * S', streaming stores ----
    u64 c2 = pk2(c, c);
#pragma unroll
    for (int kk = 0; kk < 8; kk++){
        u64 wx = mul2(S[kk].x, c2);
        u64 wy = mul2(S[kk].y, c2);
        float4 f;
        up2(wx, f.x, f.y);
        up2(wy, f.z, f.w);
        __stcs((float4*)(sout + sbase + (size_t)(k0 + kk) * DV + v0), f);
    }
}

extern "C" void kernel_launch(void* const* d_in, const int* in_sizes, int n_in,
                              void* d_out, int out_size)
{
    const float* q    = (const float*)d_in[0];
    const float* k    = (const float*)d_in[1];
    const float* v    = (const float*)d_in[2];
    const float* g    = (const float*)d_in[3];
    const float* beta = (const float*)d_in[4];
    const float* s0   = (const float*)d_in[5];
    float* out  = (float*)d_out;
    float* sout = out + (size_t)NBH * TT * DV;   // state follows the T outputs

    gdn_step_kernel<<<NBH * 4, 256>>>(q, k, v, g, beta, s0, out, sout);
}